// round 12
// baseline (speedup 1.0000x reference)
#include <cuda_runtime.h>
#include <math.h>
#include <stdint.h>

#define HD 128
#define NN 256
#define NB 16

// Scratch (allocation-free rule: __device__ globals)
__device__ float g_h[NN][HD];    // layer-2 output (relu)
__device__ float g_P[32][HD];    // per-block partial sums of dinv*h (scan)
__device__ float g_v3[NB][HD];   // post-layer-3 vector per batch b>=1
__device__ float g_A0[NN][HD];   // h3 @ W1a + b1   (batch 0)
__device__ float g_B0[NN][HD];   // h3 @ W1b        (batch 0)
__device__ float g_pb[NB];       // constant edge prob per batch (b>=1)

// 32KB stage load via cp.async (8 x 16B per thread, 256 threads)
__device__ __forceinline__ void cp_stage(uint32_t dst, const float* src, int tid) {
    const char* s = (const char*)src + tid * 16;
    uint32_t d = dst + tid * 16;
#pragma unroll
    for (int i = 0; i < 8; i++)
        asm volatile("cp.async.cg.shared.global [%0], [%1], 16;"
                     :: "r"(d + i * 4096), "l"(s + i * 4096));
    asm volatile("cp.async.commit_group;" ::: "memory");
}
#define CPWG4() asm volatile("cp.async.wait_group 4;" ::: "memory")
#define CPWG3() asm volatile("cp.async.wait_group 3;" ::: "memory")
#define CPWG2() asm volatile("cp.async.wait_group 2;" ::: "memory")
#define CPWG1() asm volatile("cp.async.wait_group 1;" ::: "memory")
#define CPWG0() asm volatile("cp.async.wait_group 0;" ::: "memory")

// ---------------------------------------------------------------------------
// K1: blocks 0..31 : batch-0. emb/u via direct warp-k-split LDG (no staging),
//                    only the 64KB layer-2 weight staged (2 cp.async groups,
//                    overlapped with closed-form L1 + scan). 4 serial steps.
//     block 32     : ALL 15 chains in one block (warp-per-2-batches), weights
//                    staged once through a ring-5 of 32KB buffers (7 groups).
// grid 33 x 256, dynamic smem 160KB
// ---------------------------------------------------------------------------
__global__ void __launch_bounds__(256, 1)
k1(const float* __restrict__ z, const float* __restrict__ We,
   const float* __restrict__ be, const float* __restrict__ Wg,
   const float* __restrict__ bg) {
    extern __shared__ __align__(16) float buf[];   // 5 x 8192 floats
    __shared__ __align__(16) float gs[8][HD];
    __shared__ __align__(16) float hs[8][HD];
    __shared__ __align__(16) float4 pred[8][32];   // per-warp partials
    __shared__ __align__(16) float vvs[17][HD];    // chain vectors (row 16 dummy)
    __shared__ __align__(16) float zsall[16][64];
    __shared__ float zs[64];
    __shared__ float vv[HD];
    __shared__ float uu[HD];
    __shared__ float ds[NN];
    int tid = threadIdx.x, bk = blockIdx.x;
    int warp = tid >> 5, lane = tid & 31;
    uint32_t sb = (uint32_t)__cvta_generic_to_shared(buf);

    // let k2 launch + prefetch its weights while we run (PDL)
    cudaTriggerProgrammaticLaunchCompletion();

    if (bk < 32) {
        // ---- batch-0 ----
        // stage layer-2 weight halves (only staging this block does)
        cp_stage(sb,          Wg + HD * HD,           tid);   // g0 -> buf0
        cp_stage(sb + 32768u, Wg + HD * HD + 64 * HD, tid);   // g1 -> buf1
        if (tid < 64) zs[tid] = z[tid];
        ds[tid] = rsqrtf((float)(tid + 1));
        __syncthreads();

        const float4* We4  = (const float4*)We;
        const float4* Wg04 = (const float4*)Wg;

        // emb: warp k-split over We (8 k per warp), direct LDG.128
        {
            float4 pe = make_float4(0.f, 0.f, 0.f, 0.f);
#pragma unroll
            for (int i = 0; i < 8; i++) {
                int k = warp * 8 + i;
                float zk = zs[k];
                float4 w4 = We4[k * 32 + lane];
                pe.x = fmaf(zk, w4.x, pe.x); pe.y = fmaf(zk, w4.y, pe.y);
                pe.z = fmaf(zk, w4.z, pe.z); pe.w = fmaf(zk, w4.w, pe.w);
            }
            pred[warp][lane] = pe;
        }
        __syncthreads();
        if (tid < 32) {
            float4 s = pred[0][tid];
#pragma unroll
            for (int w = 1; w < 8; w++) {
                float4 p = pred[w][tid];
                s.x += p.x; s.y += p.y; s.z += p.z; s.w += p.w;
            }
            float4 b4 = ((const float4*)be)[tid];
            s.x += b4.x; s.y += b4.y; s.z += b4.z; s.w += b4.w;
            ((float4*)vv)[tid] = s;
        }
        __syncthreads();

        // u = vv @ Wg0: warp k-split (16 k per warp), direct LDG.128
        {
            float4 pu = make_float4(0.f, 0.f, 0.f, 0.f);
#pragma unroll
            for (int i = 0; i < 16; i++) {
                int k = warp * 16 + i;
                float vk = vv[k];
                float4 w4 = Wg04[k * 32 + lane];
                pu.x = fmaf(vk, w4.x, pu.x); pu.y = fmaf(vk, w4.y, pu.y);
                pu.z = fmaf(vk, w4.z, pu.z); pu.w = fmaf(vk, w4.w, pu.w);
            }
            pred[warp][lane] = pu;
        }
        __syncthreads();
        if (tid < 32) {
            float4 s = pred[0][tid];
#pragma unroll
            for (int w = 1; w < 8; w++) {
                float4 p = pred[w][tid];
                s.x += p.x; s.y += p.y; s.z += p.z; s.w += p.w;
            }
            ((float4*)uu)[tid] = s;
        }
        __syncthreads();

        // closed-form layer-1 + exclusive dinv-scan (overlaps cp.async arrival)
        if (tid < 128) {
            int d = tid;
            float uf = uu[d];
            float bg0 = bg[d];
            float c = 0.f, Dex = 0.f;
            int base = bk * 8;
            for (int j = 0; j < base + 8; j++) {
                float dv = ds[j];
                float sc = fmaf(dv, Dex, dv * dv);
                float h1 = fmaxf(fmaf(sc, uf, bg0), 0.f);
                if (j >= base) gs[j - base][d] = fmaf(dv, c, dv * dv * h1);
                c = fmaf(dv, h1, c);
                Dex += dv;
            }
        }
        __syncthreads();

        // layer-2 GEMM: warp-per-row, 2 staged halves
        float4 acc = ((const float4*)(bg + HD))[lane];
        CPWG1(); __syncthreads();
        {
            const float4* Ws4 = (const float4*)buf;
#pragma unroll 8
            for (int k = 0; k < 64; k++) {
                float g = gs[warp][k];
                float4 w = Ws4[k * 32 + lane];
                acc.x = fmaf(g, w.x, acc.x); acc.y = fmaf(g, w.y, acc.y);
                acc.z = fmaf(g, w.z, acc.z); acc.w = fmaf(g, w.w, acc.w);
            }
        }
        CPWG0(); __syncthreads();
        {
            const float4* Ws4 = (const float4*)(buf + 8192);
#pragma unroll 8
            for (int k = 0; k < 64; k++) {
                float g = gs[warp][64 + k];
                float4 w = Ws4[k * 32 + lane];
                acc.x = fmaf(g, w.x, acc.x); acc.y = fmaf(g, w.y, acc.y);
                acc.z = fmaf(g, w.z, acc.z); acc.w = fmaf(g, w.w, acc.w);
            }
        }
        acc.x = fmaxf(acc.x, 0.f); acc.y = fmaxf(acc.y, 0.f);
        acc.z = fmaxf(acc.z, 0.f); acc.w = fmaxf(acc.w, 0.f);
        int base = bk * 8;
        ((float4*)&g_h[base + warp][0])[lane] = acc;
        float dj = ds[base + warp];
        ((float4*)&hs[warp][0])[lane] = make_float4(acc.x * dj, acc.y * dj, acc.z * dj, acc.w * dj);
        __syncthreads();
        if (tid < HD) {
            float sum = 0.f;
#pragma unroll
            for (int w = 0; w < 8; w++) sum += hs[w][tid];
            g_P[bk][tid] = sum;
        }
    } else {
        // ---- ALL 15 chains in one block: warp w -> batches w+1, w+9 ----
        const float* srcs[7] = { We,
            Wg,               Wg + 64 * HD,
            Wg + HD * HD,     Wg + HD * HD + 64 * HD,
            Wg + 2 * HD * HD, Wg + 2 * HD * HD + 64 * HD };
#pragma unroll
        for (int i = 0; i < 5; i++) cp_stage(sb + i * 32768u, srcs[i], tid);
        // z rows for b=1..15 into zsall[0..14]
        for (int i = tid; i < 15 * 64; i += 256)
            zsall[i >> 6][i & 63] = z[64 + i];
        int bA = warp + 1;
        int bB = warp + 9;                 // 9..16 (16 = dummy)
        bool hasB = (warp < 7);
        int bBs = hasB ? bB : 16;

        // step 0: embeddings (needs g0 = We in buf0)
        CPWG4(); __syncthreads();
        {
            const float4* W4 = (const float4*)buf;
            float4 aA = make_float4(0.f, 0.f, 0.f, 0.f);
            float4 aB = make_float4(0.f, 0.f, 0.f, 0.f);
#pragma unroll 8
            for (int k = 0; k < 64; k++) {
                float4 w4 = W4[k * 32 + lane];
                float vA = zsall[bA - 1][k];
                float vB = zsall[bBs - 1][k];
                aA.x = fmaf(vA, w4.x, aA.x); aA.y = fmaf(vA, w4.y, aA.y);
                aA.z = fmaf(vA, w4.z, aA.z); aA.w = fmaf(vA, w4.w, aA.w);
                aB.x = fmaf(vB, w4.x, aB.x); aB.y = fmaf(vB, w4.y, aB.y);
                aB.z = fmaf(vB, w4.z, aB.z); aB.w = fmaf(vB, w4.w, aB.w);
            }
            float4 be4 = ((const float4*)be)[lane];
            aA.x += be4.x; aA.y += be4.y; aA.z += be4.z; aA.w += be4.w;
            aB.x += be4.x; aB.y += be4.y; aB.z += be4.z; aB.w += be4.w;
            ((float4*)&vvs[bA][0])[lane] = aA;
            if (hasB) ((float4*)&vvs[bB][0])[lane] = aB;
        }
        __syncthreads();
        cp_stage(sb, srcs[5], tid);        // g5 -> buf0

        // steps 1..3: GCN layers (layer l uses buffers per ring schedule)
#pragma unroll
        for (int l = 0; l < 3; l++) {
            if (l == 0)      { CPWG3(); }
            else if (l == 1) { CPWG2(); }
            else             { CPWG0(); }
            __syncthreads();
            const float4* WA4;
            const float4* WB4;
            if (l == 0)      { WA4 = (const float4*)(buf + 1 * 8192); WB4 = (const float4*)(buf + 2 * 8192); }
            else if (l == 1) { WA4 = (const float4*)(buf + 3 * 8192); WB4 = (const float4*)(buf + 4 * 8192); }
            else             { WA4 = (const float4*)(buf + 0 * 8192); WB4 = (const float4*)(buf + 1 * 8192); }
            float4 bg4 = ((const float4*)(bg + l * HD))[lane];
            float4 aA = bg4, aB = bg4;
#pragma unroll 8
            for (int k = 0; k < 64; k++) {
                float4 w4 = WA4[k * 32 + lane];
                float vA = vvs[bA][k];
                float vB = vvs[bBs][k];
                aA.x = fmaf(vA, w4.x, aA.x); aA.y = fmaf(vA, w4.y, aA.y);
                aA.z = fmaf(vA, w4.z, aA.z); aA.w = fmaf(vA, w4.w, aA.w);
                aB.x = fmaf(vB, w4.x, aB.x); aB.y = fmaf(vB, w4.y, aB.y);
                aB.z = fmaf(vB, w4.z, aB.z); aB.w = fmaf(vB, w4.w, aB.w);
            }
#pragma unroll 8
            for (int k = 0; k < 64; k++) {
                float4 w4 = WB4[k * 32 + lane];
                float vA = vvs[bA][64 + k];
                float vB = vvs[bBs][64 + k];
                aA.x = fmaf(vA, w4.x, aA.x); aA.y = fmaf(vA, w4.y, aA.y);
                aA.z = fmaf(vA, w4.z, aA.z); aA.w = fmaf(vA, w4.w, aA.w);
                aB.x = fmaf(vB, w4.x, aB.x); aB.y = fmaf(vB, w4.y, aB.y);
                aB.z = fmaf(vB, w4.z, aB.z); aB.w = fmaf(vB, w4.w, aB.w);
            }
            aA.x = fmaxf(aA.x, 0.f); aA.y = fmaxf(aA.y, 0.f);
            aA.z = fmaxf(aA.z, 0.f); aA.w = fmaxf(aA.w, 0.f);
            aB.x = fmaxf(aB.x, 0.f); aB.y = fmaxf(aB.y, 0.f);
            aB.z = fmaxf(aB.z, 0.f); aB.w = fmaxf(aB.w, 0.f);
            if (l < 2) {
                ((float4*)&vvs[bA][0])[lane] = aA;
                if (hasB) ((float4*)&vvs[bB][0])[lane] = aB;
            } else {
                ((float4*)&g_v3[bA][0])[lane] = aA;
                if (hasB) ((float4*)&g_v3[bB][0])[lane] = aB;
            }
            __syncthreads();
            if (l == 0) cp_stage(sb + 32768u, srcs[6], tid);   // g6 -> buf1
        }
    }
}

// ---------------------------------------------------------------------------
// K2: blocks 0..63 : scan -> layer-3 GEMM+relu -> W1a|W1b GEMM (4 stages).
//     blocks 64..78: chain logits for b=1..15 (v3 @ W1a/W1b -> sigmoid).
// PDL: weight prefetch happens BEFORE the grid-dependency sync.
// grid 79 x 256, dynamic smem 128KB
// ---------------------------------------------------------------------------
__global__ void __launch_bounds__(256, 1)
k2(const float* __restrict__ Wg2, const float* __restrict__ bg2,
   const float* __restrict__ W1a, const float* __restrict__ W1b,
   const float* __restrict__ b1, const float* __restrict__ W2,
   const float* __restrict__ b2) {
    extern __shared__ __align__(16) float buf[];   // 4 x 8192 floats
    __shared__ __align__(16) float gs[8][HD];
    __shared__ __align__(16) float hs[8][HD];
    __shared__ float vv[HD];
    __shared__ float red[2][HD];
    __shared__ float wsum[8];
    int tid = threadIdx.x, blk = blockIdx.x;
    int d = tid & 127, hf = tid >> 7;
    int warp = tid >> 5, lane = tid & 31;
    uint32_t sb = (uint32_t)__cvta_generic_to_shared(buf);

    // let k3 launch + stage its constants while we run (PDL)
    cudaTriggerProgrammaticLaunchCompletion();

    if (blk < 64) {
        int bk2 = blk >> 1, sel = blk & 1;
        int base = bk2 * 8;
        const float* WX = sel ? W1b : W1a;
        const float* srcs[4] = { Wg2, Wg2 + 64 * HD, WX, WX + 64 * HD };
#pragma unroll
        for (int i = 0; i < 4; i++) cp_stage(sb + i * 32768u, srcs[i], tid);

        // wait for k1's g_h / g_P to be visible (weights already in flight)
        cudaGridDependencySynchronize();

        // prologue: prefetched scan (overlaps in-flight loads)
        if (tid < 128) {
            float hr[8];
#pragma unroll
            for (int j = 0; j < 8; j++) hr[j] = g_h[base + j][tid];
            float ca[4] = {0.f, 0.f, 0.f, 0.f};
#pragma unroll
            for (int p = 0; p < 32; p++) {
                float v = g_P[p][tid];
                ca[p & 3] += (p < bk2) ? v : 0.f;
            }
            float c = (ca[0] + ca[1]) + (ca[2] + ca[3]);
#pragma unroll
            for (int j = 0; j < 8; j++) {
                float dv = rsqrtf((float)(base + j + 1));
                gs[j][tid] = fmaf(dv, c, dv * dv * hr[j]);
                c = fmaf(dv, hr[j], c);
            }
        }
        float4 acc = ((const float4*)bg2)[lane];
        float4 aX = sel ? make_float4(0.f, 0.f, 0.f, 0.f)
                        : ((const float4*)b1)[lane];
#pragma unroll
        for (int s = 0; s < 4; s++) {
            if (s == 0) { CPWG3(); } else if (s == 1) { CPWG2(); }
            else if (s == 2) { CPWG1(); } else { CPWG0(); }
            __syncthreads();
            const float4* Ws4 = (const float4*)(buf + s * 8192);
            const float* in = (s < 2) ? &gs[warp][0] : &hs[warp][0];
            int ko = (s & 1) * 64;
            float4 a = (s < 2) ? acc : aX;
#pragma unroll 8
            for (int k = 0; k < 64; k++) {
                float g = in[ko + k];
                float4 w = Ws4[k * 32 + lane];
                a.x = fmaf(g, w.x, a.x); a.y = fmaf(g, w.y, a.y);
                a.z = fmaf(g, w.z, a.z); a.w = fmaf(g, w.w, a.w);
            }
            if (s < 2) acc = a; else aX = a;
            if (s == 1) {   // h3 = relu(acc)
                acc.x = fmaxf(acc.x, 0.f); acc.y = fmaxf(acc.y, 0.f);
                acc.z = fmaxf(acc.z, 0.f); acc.w = fmaxf(acc.w, 0.f);
                ((float4*)&hs[warp][0])[lane] = acc;
            }
            __syncthreads();
        }
        if (sel) ((float4*)&g_B0[base + warp][0])[lane] = aX;
        else     ((float4*)&g_A0[base + warp][0])[lane] = aX;
    } else {
        // chain logit for b = blk-63
        int b = blk - 63;
        const float* srcs[4] = { W1a, W1a + 64 * HD, W1b, W1b + 64 * HD };
#pragma unroll
        for (int i = 0; i < 4; i++) cp_stage(sb + i * 32768u, srcs[i], tid);

        cudaGridDependencySynchronize();   // need g_v3 from k1
        if (tid < 128) vv[d] = g_v3[b][d];

        float aAf = 0.f;
        // step A: W1a (needs g0,g1)
        CPWG2(); __syncthreads();
        {
            const float* B = buf + (hf ? 1 : 0) * 8192;
            int kb = hf * 64;
            float p0 = 0.f, p1 = 0.f;
#pragma unroll 8
            for (int kk = 0; kk < 64; kk += 2) {
                p0 = fmaf(vv[kb + kk],     B[kk * HD + d],       p0);
                p1 = fmaf(vv[kb + kk + 1], B[(kk + 1) * HD + d], p1);
            }
            red[hf][d] = p0 + p1;
        }
        __syncthreads();
        if (tid < 128) aAf = red[0][d] + red[1][d] + b1[d];

        // step B: W1b (needs g2,g3)
        CPWG0(); __syncthreads();
        {
            const float* B = buf + (hf ? 3 : 2) * 8192;
            int kb = hf * 64;
            float p0 = 0.f, p1 = 0.f;
#pragma unroll 8
            for (int kk = 0; kk < 64; kk += 2) {
                p0 = fmaf(vv[kb + kk],     B[kk * HD + d],       p0);
                p1 = fmaf(vv[kb + kk + 1], B[(kk + 1) * HD + d], p1);
            }
            red[hf][d] = p0 + p1;
        }
        __syncthreads();
        float t = 0.f;
        if (tid < 128) t = fmaxf(aAf + red[0][d] + red[1][d], 0.f) * W2[d];
        for (int off = 16; off > 0; off >>= 1)
            t += __shfl_down_sync(0xffffffffu, t, off);
        if ((tid & 31) == 0) wsum[tid >> 5] = t;
        __syncthreads();
        if (tid == 0) {
            float ssum = wsum[0] + wsum[1] + wsum[2] + wsum[3]
                       + wsum[4] + wsum[5] + wsum[6] + wsum[7] + b2[0];
            g_pb[b] = 1.f / (1.f + __expf(-ssum));
        }
    }
}

// ---------------------------------------------------------------------------
// K3: blocks 0..135 : batch-0 pairwise tiles (16x16, upper triangle, mirrored)
//     blocks 136..147: constant fill for b>=1 (320 rows each, diag 0)
// PDL: W2/b2 staged before the grid-dependency sync. grid 148 x 256
// ---------------------------------------------------------------------------
__global__ void k3(const float* __restrict__ W2, const float* __restrict__ b2,
                   float* __restrict__ out) {
    int tid = threadIdx.x;
    int blk = blockIdx.x;
    if (blk < 136) {
        int ti = 0, rem = blk;
        while (rem >= 16 - ti) { rem -= 16 - ti; ti++; }
        int tj = ti + rem;

        __shared__ __align__(16) float a_sh[16][132];
        __shared__ __align__(16) float b_sh[16][132];
        __shared__ __align__(16) float w2s[HD];
        __shared__ float b2s;
        __shared__ float tile[16][17];
        // stage inputs that don't depend on k2 BEFORE the dependency sync
        if (tid < HD) w2s[tid] = W2[tid];
        if (tid == 0) b2s = b2[0];

        cudaGridDependencySynchronize();   // need g_A0 / g_B0 from k2

        for (int i = tid; i < 512; i += 256) {
            int r = i >> 5, d4 = i & 31;
            ((float4*)&a_sh[r][0])[d4] = ((const float4*)&g_A0[ti * 16 + r][0])[d4];
            ((float4*)&b_sh[r][0])[d4] = ((const float4*)&g_B0[tj * 16 + r][0])[d4];
        }
        __syncthreads();

        int il = tid >> 4, jl = tid & 15;
        const float4* a4 = (const float4*)&a_sh[il][0];
        const float4* b4 = (const float4*)&b_sh[jl][0];
        const float4* w4 = (const float4*)w2s;
        float ac0 = 0.f, ac1 = 0.f, ac2 = 0.f, ac3 = 0.f;
#pragma unroll
        for (int qd = 0; qd < 8; qd++) {
            { float4 a=a4[qd],    b=b4[qd],    w=w4[qd];
              ac0 = fmaf(fmaxf(a.x+b.x,0.f),w.x,ac0); ac0 = fmaf(fmaxf(a.y+b.y,0.f),w.y,ac0);
              ac0 = fmaf(fmaxf(a.z+b.z,0.f),w.z,ac0); ac0 = fmaf(fmaxf(a.w+b.w,0.f),w.w,ac0); }
            { float4 a=a4[qd+8],  b=b4[qd+8],  w=w4[qd+8];
              ac1 = fmaf(fmaxf(a.x+b.x,0.f),w.x,ac1); ac1 = fmaf(fmaxf(a.y+b.y,0.f),w.y,ac1);
              ac1 = fmaf(fmaxf(a.z+b.z,0.f),w.z,ac1); ac1 = fmaf(fmaxf(a.w+b.w,0.f),w.w,ac1); }
            { float4 a=a4[qd+16], b=b4[qd+16], w=w4[qd+16];
              ac2 = fmaf(fmaxf(a.x+b.x,0.f),w.x,ac2); ac2 = fmaf(fmaxf(a.y+b.y,0.f),w.y,ac2);
              ac2 = fmaf(fmaxf(a.z+b.z,0.f),w.z,ac2); ac2 = fmaf(fmaxf(a.w+b.w,0.f),w.w,ac2); }
            { float4 a=a4[qd+24], b=b4[qd+24], w=w4[qd+24];
              ac3 = fmaf(fmaxf(a.x+b.x,0.f),w.x,ac3); ac3 = fmaf(fmaxf(a.y+b.y,0.f),w.y,ac3);
              ac3 = fmaf(fmaxf(a.z+b.z,0.f),w.z,ac3); ac3 = fmaf(fmaxf(a.w+b.w,0.f),w.w,ac3); }
        }
        float accv = (ac0 + ac1) + (ac2 + ac3);
        tile[il][jl] = 1.f / (1.f + __expf(-(accv + b2s)));
        __syncthreads();

        int r = tid >> 4, c = tid & 15;
        if (ti == tj) {
            float vo = (r < c) ? tile[r][c] : ((r > c) ? tile[c][r] : 0.f);
            out[((size_t)(ti * 16 + r)) * NN + ti * 16 + c] = vo;
        } else {
            out[((size_t)(ti * 16 + r)) * NN + tj * 16 + c] = tile[r][c];
            out[((size_t)(tj * 16 + r)) * NN + ti * 16 + c] = tile[c][r];
        }
    } else {
        __shared__ float pbs[NB];
        cudaGridDependencySynchronize();   // need g_pb from k2
        if (tid < NB) pbs[tid] = g_pb[tid];
        __syncthreads();
        int fid = blk - 136;
        int f4base = fid * 20480;          // 320 rows * 64 float4 per block
#pragma unroll 4
        for (int t = 0; t < 80; t++) {
            int idx = f4base + t * 256 + tid;
            int gr = idx >> 6;             // fill row 0..3839
            int c4 = idx & 63;
            int b = (gr >> 8) + 1;
            int i = gr & 255;
            float p = pbs[b];
            int j0 = c4 * 4;
            float4 vo;
            vo.x = (i == j0 + 0) ? 0.f : p;
            vo.y = (i == j0 + 1) ? 0.f : p;
            vo.z = (i == j0 + 2) ? 0.f : p;
            vo.w = (i == j0 + 3) ? 0.f : p;
            ((float4*)out)[((size_t)b * NN * NN + (size_t)i * NN) / 4 + c4] = vo;
        }
    }
}

// ---------------------------------------------------------------------------
extern "C" void kernel_launch(void* const* d_in, const int* in_sizes, int n_in,
                              void* d_out, int out_size) {
    const float* z   = (const float*)d_in[0];
    const float* We  = (const float*)d_in[1];
    const float* be  = (const float*)d_in[2];
    const float* Wg  = (const float*)d_in[3];
    const float* bg  = (const float*)d_in[4];
    const float* W1a = (const float*)d_in[5];
    const float* W1b = (const float*)d_in[6];
    const float* b1  = (const float*)d_in[7];
    const float* W2  = (const float*)d_in[8];
    const float* b2  = (const float*)d_in[9];
    float* out = (float*)d_out;

    cudaFuncSetAttribute(k1, cudaFuncAttributeMaxDynamicSharedMemorySize, 163840);
    cudaFuncSetAttribute(k2, cudaFuncAttributeMaxDynamicSharedMemorySize, 131072);

    // k1: normal launch
    k1<<<33, 256, 163840>>>(z, We, be, Wg, bg);

    // k2, k3: programmatic dependent launches
    cudaLaunchAttribute attrs[1];
    attrs[0].id = cudaLaunchAttributeProgrammaticStreamSerialization;
    attrs[0].val.programmaticStreamSerializationAllowed = 1;

    {
        cudaLaunchConfig_t cfg = {};
        cfg.gridDim = dim3(79);
        cfg.blockDim = dim3(256);
        cfg.dynamicSmemBytes = 131072;
        cfg.stream = 0;
        cfg.attrs = attrs;
        cfg.numAttrs = 1;
        cudaLaunchKernelEx(&cfg, k2, Wg + 2 * HD * HD, bg + 2 * HD,
                           W1a, W1b, b1, W2, b2);
    }
    {
        cudaLaunchConfig_t cfg = {};
        cfg.gridDim = dim3(148);
        cfg.blockDim = dim3(256);
        cfg.dynamicSmemBytes = 0;
        cfg.stream = 0;
        cfg.attrs = attrs;
        cfg.numAttrs = 1;
        cudaLaunchKernelEx(&cfg, k3, W2, b2, out);
    }
}

// round 14
// speedup vs baseline: 1.0585x; 1.0585x over previous
#include <cuda_runtime.h>
#include <math.h>
#include <stdint.h>

#define HD 128
#define NN 256
#define NB 16

// Scratch (allocation-free rule: __device__ globals)
__device__ float g_h[NN][HD];    // layer-2 output (relu), batch 0
__device__ float g_P[32][HD];    // per-block partial sums of dinv*h (scan)
__device__ float g_A0[NN][HD];   // h3 @ W1a + b1   (batch 0)
__device__ float g_B0[NN][HD];   // h3 @ W1b        (batch 0)
__device__ float g_pb[NB];       // constant edge prob per batch (b>=1)

// 32KB stage load via cp.async (8 x 16B per thread, 256 threads)
__device__ __forceinline__ void cp_stage(uint32_t dst, const float* src, int tid) {
    const char* s = (const char*)src + tid * 16;
    uint32_t d = dst + tid * 16;
#pragma unroll
    for (int i = 0; i < 8; i++)
        asm volatile("cp.async.cg.shared.global [%0], [%1], 16;"
                     :: "r"(d + i * 4096), "l"(s + i * 4096));
    asm volatile("cp.async.commit_group;" ::: "memory");
}
#define CPWG3() asm volatile("cp.async.wait_group 3;" ::: "memory")
#define CPWG2() asm volatile("cp.async.wait_group 2;" ::: "memory")
#define CPWG1() asm volatile("cp.async.wait_group 1;" ::: "memory")
#define CPWG0() asm volatile("cp.async.wait_group 0;" ::: "memory")

// ---------------------------------------------------------------------------
// K1: batch-0 ONLY. 32 blocks: emb/u via direct warp-k-split LDG, closed-form
// layer-1 + exclusive dinv-scan (overlaps the 64KB layer-2 weight cp.async),
// layer-2 GEMM from staged smem. Emits g_h + g_P.
// grid 32 x 256, dynamic smem 64KB (2 x 32KB)
// ---------------------------------------------------------------------------
__global__ void __launch_bounds__(256, 1)
k1(const float* __restrict__ z, const float* __restrict__ We,
   const float* __restrict__ be, const float* __restrict__ Wg,
   const float* __restrict__ bg) {
    extern __shared__ __align__(16) float buf[];   // 2 x 8192 floats
    __shared__ __align__(16) float gs[8][HD];
    __shared__ __align__(16) float hs[8][HD];
    __shared__ __align__(16) float4 pred[8][32];   // per-warp partials
    __shared__ float zs[64];
    __shared__ float vv[HD];
    __shared__ float uu[HD];
    __shared__ float ds[NN];
    int tid = threadIdx.x, bk = blockIdx.x;
    int warp = tid >> 5, lane = tid & 31;
    uint32_t sb = (uint32_t)__cvta_generic_to_shared(buf);

    // let k2 launch + run its independent work while we execute (PDL)
    cudaTriggerProgrammaticLaunchCompletion();

    // stage layer-2 weight halves (the only staging this kernel does)
    cp_stage(sb,          Wg + HD * HD,           tid);   // g0 -> buf0
    cp_stage(sb + 32768u, Wg + HD * HD + 64 * HD, tid);   // g1 -> buf1
    if (tid < 64) zs[tid] = z[tid];
    ds[tid] = rsqrtf((float)(tid + 1));
    __syncthreads();

    const float4* We4  = (const float4*)We;
    const float4* Wg04 = (const float4*)Wg;

    // emb: warp k-split over We (8 k per warp), direct LDG.128
    {
        float4 pe = make_float4(0.f, 0.f, 0.f, 0.f);
#pragma unroll
        for (int i = 0; i < 8; i++) {
            int k = warp * 8 + i;
            float zk = zs[k];
            float4 w4 = We4[k * 32 + lane];
            pe.x = fmaf(zk, w4.x, pe.x); pe.y = fmaf(zk, w4.y, pe.y);
            pe.z = fmaf(zk, w4.z, pe.z); pe.w = fmaf(zk, w4.w, pe.w);
        }
        pred[warp][lane] = pe;
    }
    __syncthreads();
    if (tid < 32) {
        float4 s = pred[0][tid];
#pragma unroll
        for (int w = 1; w < 8; w++) {
            float4 p = pred[w][tid];
            s.x += p.x; s.y += p.y; s.z += p.z; s.w += p.w;
        }
        float4 b4 = ((const float4*)be)[tid];
        s.x += b4.x; s.y += b4.y; s.z += b4.z; s.w += b4.w;
        ((float4*)vv)[tid] = s;
    }
    __syncthreads();

    // u = vv @ Wg0: warp k-split (16 k per warp), direct LDG.128
    {
        float4 pu = make_float4(0.f, 0.f, 0.f, 0.f);
#pragma unroll
        for (int i = 0; i < 16; i++) {
            int k = warp * 16 + i;
            float vk = vv[k];
            float4 w4 = Wg04[k * 32 + lane];
            pu.x = fmaf(vk, w4.x, pu.x); pu.y = fmaf(vk, w4.y, pu.y);
            pu.z = fmaf(vk, w4.z, pu.z); pu.w = fmaf(vk, w4.w, pu.w);
        }
        pred[warp][lane] = pu;
    }
    __syncthreads();
    if (tid < 32) {
        float4 s = pred[0][tid];
#pragma unroll
        for (int w = 1; w < 8; w++) {
            float4 p = pred[w][tid];
            s.x += p.x; s.y += p.y; s.z += p.z; s.w += p.w;
        }
        ((float4*)uu)[tid] = s;
    }
    __syncthreads();

    // closed-form layer-1 + exclusive dinv-scan (overlaps cp.async arrival)
    if (tid < 128) {
        int d = tid;
        float uf = uu[d];
        float bg0 = bg[d];
        float c = 0.f, Dex = 0.f;
        int base = bk * 8;
        for (int j = 0; j < base + 8; j++) {
            float dv = ds[j];
            float sc = fmaf(dv, Dex, dv * dv);
            float h1 = fmaxf(fmaf(sc, uf, bg0), 0.f);
            if (j >= base) gs[j - base][d] = fmaf(dv, c, dv * dv * h1);
            c = fmaf(dv, h1, c);
            Dex += dv;
        }
    }
    __syncthreads();

    // layer-2 GEMM: warp-per-row, 2 staged halves
    float4 acc = ((const float4*)(bg + HD))[lane];
    CPWG1(); __syncthreads();
    {
        const float4* Ws4 = (const float4*)buf;
#pragma unroll 8
        for (int k = 0; k < 64; k++) {
            float g = gs[warp][k];
            float4 w = Ws4[k * 32 + lane];
            acc.x = fmaf(g, w.x, acc.x); acc.y = fmaf(g, w.y, acc.y);
            acc.z = fmaf(g, w.z, acc.z); acc.w = fmaf(g, w.w, acc.w);
        }
    }
    CPWG0(); __syncthreads();
    {
        const float4* Ws4 = (const float4*)(buf + 8192);
#pragma unroll 8
        for (int k = 0; k < 64; k++) {
            float g = gs[warp][64 + k];
            float4 w = Ws4[k * 32 + lane];
            acc.x = fmaf(g, w.x, acc.x); acc.y = fmaf(g, w.y, acc.y);
            acc.z = fmaf(g, w.z, acc.z); acc.w = fmaf(g, w.w, acc.w);
        }
    }
    acc.x = fmaxf(acc.x, 0.f); acc.y = fmaxf(acc.y, 0.f);
    acc.z = fmaxf(acc.z, 0.f); acc.w = fmaxf(acc.w, 0.f);
    int base = bk * 8;
    ((float4*)&g_h[base + warp][0])[lane] = acc;
    float dj = ds[base + warp];
    ((float4*)&hs[warp][0])[lane] = make_float4(acc.x * dj, acc.y * dj, acc.z * dj, acc.w * dj);
    __syncthreads();
    if (tid < HD) {
        float sum = 0.f;
#pragma unroll
        for (int w = 0; w < 8; w++) sum += hs[w][tid];
        g_P[bk][tid] = sum;
    }
}

// ---------------------------------------------------------------------------
// K2: blocks 0..63 : scan -> layer-3 GEMM+relu -> W1a|W1b GEMM (4 stages);
//                    waits on k1 only AFTER issuing its weight prefetch.
//     blocks 64..78: FULL chain for b = blk-63 (emb -> 3 layers -> W1a/W1b
//                    -> logit -> g_pb). Depends ONLY on z + weights — runs
//                    fully concurrent with k1 (no gridDependencySynchronize).
//                    11 half-stages through a ring-4 of 32KB buffers.
// grid 79 x 256, dynamic smem 128KB
// ---------------------------------------------------------------------------
__global__ void __launch_bounds__(256, 1)
k2(const float* __restrict__ z, const float* __restrict__ We,
   const float* __restrict__ be, const float* __restrict__ Wg,
   const float* __restrict__ bg, const float* __restrict__ W1a,
   const float* __restrict__ W1b, const float* __restrict__ b1,
   const float* __restrict__ W2, const float* __restrict__ b2) {
    extern __shared__ __align__(16) float buf[];   // 4 x 8192 floats
    __shared__ __align__(16) float gs[8][HD];
    __shared__ __align__(16) float hs[8][HD];
    __shared__ float zs[64];
    __shared__ float vv[HD];
    __shared__ float red[2][HD];
    __shared__ float wsum[8];
    int tid = threadIdx.x, blk = blockIdx.x;
    int d = tid & 127, hf = tid >> 7;
    int warp = tid >> 5, lane = tid & 31;
    uint32_t sb = (uint32_t)__cvta_generic_to_shared(buf);
    const float* Wg2 = Wg + 2 * HD * HD;

    // let k3 launch + stage its constants while we run (PDL)
    cudaTriggerProgrammaticLaunchCompletion();

    if (blk < 64) {
        int bk2 = blk >> 1, sel = blk & 1;
        int base = bk2 * 8;
        const float* WX = sel ? W1b : W1a;
        const float* srcs[4] = { Wg2, Wg2 + 64 * HD, WX, WX + 64 * HD };
#pragma unroll
        for (int i = 0; i < 4; i++) cp_stage(sb + i * 32768u, srcs[i], tid);

        // wait for k1's g_h / g_P to be visible (weights already in flight)
        cudaGridDependencySynchronize();

        // prologue: prefetched scan (overlaps in-flight loads)
        if (tid < 128) {
            float hr[8];
#pragma unroll
            for (int j = 0; j < 8; j++) hr[j] = g_h[base + j][tid];
            float ca[4] = {0.f, 0.f, 0.f, 0.f};
#pragma unroll
            for (int p = 0; p < 32; p++) {
                float v = g_P[p][tid];
                ca[p & 3] += (p < bk2) ? v : 0.f;
            }
            float c = (ca[0] + ca[1]) + (ca[2] + ca[3]);
#pragma unroll
            for (int j = 0; j < 8; j++) {
                float dv = rsqrtf((float)(base + j + 1));
                gs[j][tid] = fmaf(dv, c, dv * dv * hr[j]);
                c = fmaf(dv, hr[j], c);
            }
        }
        float4 acc = ((const float4*)(bg + 2 * HD))[lane];
        float4 aX = sel ? make_float4(0.f, 0.f, 0.f, 0.f)
                        : ((const float4*)b1)[lane];
#pragma unroll
        for (int s = 0; s < 4; s++) {
            if (s == 0) { CPWG3(); } else if (s == 1) { CPWG2(); }
            else if (s == 2) { CPWG1(); } else { CPWG0(); }
            __syncthreads();
            const float4* Ws4 = (const float4*)(buf + s * 8192);
            const float* in = (s < 2) ? &gs[warp][0] : &hs[warp][0];
            int ko = (s & 1) * 64;
            float4 a = (s < 2) ? acc : aX;
#pragma unroll 8
            for (int k = 0; k < 64; k++) {
                float g = in[ko + k];
                float4 w = Ws4[k * 32 + lane];
                a.x = fmaf(g, w.x, a.x); a.y = fmaf(g, w.y, a.y);
                a.z = fmaf(g, w.z, a.z); a.w = fmaf(g, w.w, a.w);
            }
            if (s < 2) acc = a; else aX = a;
            if (s == 1) {   // h3 = relu(acc)
                acc.x = fmaxf(acc.x, 0.f); acc.y = fmaxf(acc.y, 0.f);
                acc.z = fmaxf(acc.z, 0.f); acc.w = fmaxf(acc.w, 0.f);
                ((float4*)&hs[warp][0])[lane] = acc;
            }
            __syncthreads();
        }
        if (sel) ((float4*)&g_B0[base + warp][0])[lane] = aX;
        else     ((float4*)&g_A0[base + warp][0])[lane] = aX;
    } else {
        // ---- full chain for batch b = blk-63 (independent of k1) ----
        int b = blk - 63;
        const float* srcs[11] = { We,
            Wg,               Wg + 64 * HD,
            Wg + HD * HD,     Wg + HD * HD + 64 * HD,
            Wg2,              Wg2 + 64 * HD,
            W1a,              W1a + 64 * HD,
            W1b,              W1b + 64 * HD };
#pragma unroll
        for (int i = 0; i < 4; i++) cp_stage(sb + i * 32768u, srcs[i], tid);
        if (tid < 64) zs[tid] = z[b * 64 + tid];
        float accL = 0.f, aA = 0.f, aB = 0.f, aAf = 0.f;
#pragma unroll
        for (int s = 0; s < 11; s++) {
            if (s <= 7) { CPWG3(); } else if (s == 8) { CPWG2(); }
            else if (s == 9) { CPWG1(); } else { CPWG0(); }
            __syncthreads();
            const float* B = buf + (s & 3) * 8192;
            if (s == 0) {
                float p0 = 0.f, p1 = 0.f; int kb = hf * 32;
#pragma unroll 8
                for (int kk = 0; kk < 32; kk += 2) {
                    p0 = fmaf(zs[kb + kk],     B[(kb + kk) * HD + d],     p0);
                    p1 = fmaf(zs[kb + kk + 1], B[(kb + kk + 1) * HD + d], p1);
                }
                red[hf][d] = p0 + p1;
                __syncthreads();
                if (tid < 128) vv[d] = red[0][d] + red[1][d] + be[d];
            } else {
                int g = (s - 1) >> 1, hh = (s - 1) & 1;
                float p0 = 0.f, p1 = 0.f; int kb = hf * 32;
#pragma unroll 8
                for (int kk = 0; kk < 32; kk += 2) {
                    p0 = fmaf(vv[hh * 64 + kb + kk],     B[(kb + kk) * HD + d],     p0);
                    p1 = fmaf(vv[hh * 64 + kb + kk + 1], B[(kb + kk + 1) * HD + d], p1);
                }
                float pt = p0 + p1;
                if (s <= 6) accL += pt;
                else if (s <= 8) aA += pt;
                else aB += pt;
                if (hh == 1 && g < 3) {        // GCN layer boundary
                    red[hf][d] = accL;
                    __syncthreads();
                    if (tid < 128) vv[d] = fmaxf(red[0][d] + red[1][d] + bg[g * HD + d], 0.f);
                    accL = 0.f;
                }
                if (s == 8) {                  // W1a done
                    red[hf][d] = aA;
                    __syncthreads();
                    if (tid < 128) aAf = red[0][d] + red[1][d] + b1[d];
                }
            }
            __syncthreads();
            if (s + 4 < 11) cp_stage(sb + ((s + 4) & 3) * 32768u, srcs[s + 4], tid);
        }
        red[hf][d] = aB;
        __syncthreads();
        float t = 0.f;
        if (tid < 128) t = fmaxf(aAf + red[0][d] + red[1][d], 0.f) * W2[d];
        for (int off = 16; off > 0; off >>= 1)
            t += __shfl_down_sync(0xffffffffu, t, off);
        if ((tid & 31) == 0) wsum[tid >> 5] = t;
        __syncthreads();
        if (tid == 0) {
            float ssum = wsum[0] + wsum[1] + wsum[2] + wsum[3]
                       + wsum[4] + wsum[5] + wsum[6] + wsum[7] + b2[0];
            g_pb[b] = 1.f / (1.f + __expf(-ssum));
        }
    }
}

// ---------------------------------------------------------------------------
// K3: blocks 0..135 : batch-0 pairwise tiles (16x16, upper triangle, mirrored)
//     blocks 136..147: constant fill for b>=1 (320 rows each, diag 0)
// PDL: W2/b2 staged before the grid-dependency sync. grid 148 x 256
// ---------------------------------------------------------------------------
__global__ void k3(const float* __restrict__ W2, const float* __restrict__ b2,
                   float* __restrict__ out) {
    int tid = threadIdx.x;
    int blk = blockIdx.x;
    if (blk < 136) {
        int ti = 0, rem = blk;
        while (rem >= 16 - ti) { rem -= 16 - ti; ti++; }
        int tj = ti + rem;

        __shared__ __align__(16) float a_sh[16][132];
        __shared__ __align__(16) float b_sh[16][132];
        __shared__ __align__(16) float w2s[HD];
        __shared__ float b2s;
        __shared__ float tile[16][17];
        // stage inputs that don't depend on k2 BEFORE the dependency sync
        if (tid < HD) w2s[tid] = W2[tid];
        if (tid == 0) b2s = b2[0];

        cudaGridDependencySynchronize();   // need g_A0 / g_B0 from k2

        for (int i = tid; i < 512; i += 256) {
            int r = i >> 5, d4 = i & 31;
            ((float4*)&a_sh[r][0])[d4] = ((const float4*)&g_A0[ti * 16 + r][0])[d4];
            ((float4*)&b_sh[r][0])[d4] = ((const float4*)&g_B0[tj * 16 + r][0])[d4];
        }
        __syncthreads();

        int il = tid >> 4, jl = tid & 15;
        const float4* a4 = (const float4*)&a_sh[il][0];
        const float4* b4 = (const float4*)&b_sh[jl][0];
        const float4* w4 = (const float4*)w2s;
        float ac0 = 0.f, ac1 = 0.f, ac2 = 0.f, ac3 = 0.f;
#pragma unroll
        for (int qd = 0; qd < 8; qd++) {
            { float4 a=a4[qd],    b=b4[qd],    w=w4[qd];
              ac0 = fmaf(fmaxf(a.x+b.x,0.f),w.x,ac0); ac0 = fmaf(fmaxf(a.y+b.y,0.f),w.y,ac0);
              ac0 = fmaf(fmaxf(a.z+b.z,0.f),w.z,ac0); ac0 = fmaf(fmaxf(a.w+b.w,0.f),w.w,ac0); }
            { float4 a=a4[qd+8],  b=b4[qd+8],  w=w4[qd+8];
              ac1 = fmaf(fmaxf(a.x+b.x,0.f),w.x,ac1); ac1 = fmaf(fmaxf(a.y+b.y,0.f),w.y,ac1);
              ac1 = fmaf(fmaxf(a.z+b.z,0.f),w.z,ac1); ac1 = fmaf(fmaxf(a.w+b.w,0.f),w.w,ac1); }
            { float4 a=a4[qd+16], b=b4[qd+16], w=w4[qd+16];
              ac2 = fmaf(fmaxf(a.x+b.x,0.f),w.x,ac2); ac2 = fmaf(fmaxf(a.y+b.y,0.f),w.y,ac2);
              ac2 = fmaf(fmaxf(a.z+b.z,0.f),w.z,ac2); ac2 = fmaf(fmaxf(a.w+b.w,0.f),w.w,ac2); }
            { float4 a=a4[qd+24], b=b4[qd+24], w=w4[qd+24];
              ac3 = fmaf(fmaxf(a.x+b.x,0.f),w.x,ac3); ac3 = fmaf(fmaxf(a.y+b.y,0.f),w.y,ac3);
              ac3 = fmaf(fmaxf(a.z+b.z,0.f),w.z,ac3); ac3 = fmaf(fmaxf(a.w+b.w,0.f),w.w,ac3); }
        }
        float accv = (ac0 + ac1) + (ac2 + ac3);
        tile[il][jl] = 1.f / (1.f + __expf(-(accv + b2s)));
        __syncthreads();

        int r = tid >> 4, c = tid & 15;
        if (ti == tj) {
            float vo = (r < c) ? tile[r][c] : ((r > c) ? tile[c][r] : 0.f);
            out[((size_t)(ti * 16 + r)) * NN + ti * 16 + c] = vo;
        } else {
            out[((size_t)(ti * 16 + r)) * NN + tj * 16 + c] = tile[r][c];
            out[((size_t)(tj * 16 + r)) * NN + ti * 16 + c] = tile[c][r];
        }
    } else {
        __shared__ float pbs[NB];
        cudaGridDependencySynchronize();   // need g_pb from k2
        if (tid < NB) pbs[tid] = g_pb[tid];
        __syncthreads();
        int fid = blk - 136;
        int f4base = fid * 20480;          // 320 rows * 64 float4 per block
#pragma unroll 4
        for (int t = 0; t < 80; t++) {
            int idx = f4base + t * 256 + tid;
            int gr = idx >> 6;             // fill row 0..3839
            int c4 = idx & 63;
            int b = (gr >> 8) + 1;
            int i = gr & 255;
            float p = pbs[b];
            int j0 = c4 * 4;
            float4 vo;
            vo.x = (i == j0 + 0) ? 0.f : p;
            vo.y = (i == j0 + 1) ? 0.f : p;
            vo.z = (i == j0 + 2) ? 0.f : p;
            vo.w = (i == j0 + 3) ? 0.f : p;
            ((float4*)out)[((size_t)b * NN * NN + (size_t)i * NN) / 4 + c4] = vo;
        }
    }
}

// ---------------------------------------------------------------------------
extern "C" void kernel_launch(void* const* d_in, const int* in_sizes, int n_in,
                              void* d_out, int out_size) {
    const float* z   = (const float*)d_in[0];
    const float* We  = (const float*)d_in[1];
    const float* be  = (const float*)d_in[2];
    const float* Wg  = (const float*)d_in[3];
    const float* bg  = (const float*)d_in[4];
    const float* W1a = (const float*)d_in[5];
    const float* W1b = (const float*)d_in[6];
    const float* b1  = (const float*)d_in[7];
    const float* W2  = (const float*)d_in[8];
    const float* b2  = (const float*)d_in[9];
    float* out = (float*)d_out;

    cudaFuncSetAttribute(k1, cudaFuncAttributeMaxDynamicSharedMemorySize, 65536);
    cudaFuncSetAttribute(k2, cudaFuncAttributeMaxDynamicSharedMemorySize, 131072);

    // k1: normal launch (batch-0 only, 32 blocks)
    k1<<<32, 256, 65536>>>(z, We, be, Wg, bg);

    // k2, k3: programmatic dependent launches
    cudaLaunchAttribute attrs[1];
    attrs[0].id = cudaLaunchAttributeProgrammaticStreamSerialization;
    attrs[0].val.programmaticStreamSerializationAllowed = 1;

    {
        cudaLaunchConfig_t cfg = {};
        cfg.gridDim = dim3(79);
        cfg.blockDim = dim3(256);
        cfg.dynamicSmemBytes = 131072;
        cfg.stream = 0;
        cfg.attrs = attrs;
        cfg.numAttrs = 1;
        cudaLaunchKernelEx(&cfg, k2, z, We, be, Wg, bg, W1a, W1b, b1, W2, b2);
    }
    {
        cudaLaunchConfig_t cfg = {};
        cfg.gridDim = dim3(148);
        cfg.blockDim = dim3(256);
        cfg.dynamicSmemBytes = 0;
        cfg.stream = 0;
        cfg.attrs = attrs;
        cfg.numAttrs = 1;
        cudaLaunchKernelEx(&cfg, k3, W2, b2, out);
    }
}

// round 16
// speedup vs baseline: 1.3368x; 1.2630x over previous
#include <cuda_runtime.h>
#include <math.h>
#include <stdint.h>

#define HD 128
#define NN 256
#define NB 16

// Scratch (allocation-free rule: __device__ globals)
__device__ float g_h[NN][HD];    // layer-2 output (relu), batch 0
__device__ float g_P[32][HD];    // per-block partial sums of dinv*h (scan)
__device__ float g_A0[NN][HD];   // h3 @ W1a + b1   (batch 0)
__device__ float g_B0[NN][HD];   // h3 @ W1b        (batch 0)
__device__ float g_pb[NB];       // constant edge prob per batch (b>=1)

// 32KB stage load via cp.async (8 x 16B per thread, 256 threads)
__device__ __forceinline__ void cp_stage(uint32_t dst, const float* src, int tid) {
    const char* s = (const char*)src + tid * 16;
    uint32_t d = dst + tid * 16;
#pragma unroll
    for (int i = 0; i < 8; i++)
        asm volatile("cp.async.cg.shared.global [%0], [%1], 16;"
                     :: "r"(d + i * 4096), "l"(s + i * 4096));
    asm volatile("cp.async.commit_group;" ::: "memory");
}
#define CPWG3() asm volatile("cp.async.wait_group 3;" ::: "memory")
#define CPWG2() asm volatile("cp.async.wait_group 2;" ::: "memory")
#define CPWG1() asm volatile("cp.async.wait_group 1;" ::: "memory")
#define CPWG0() asm volatile("cp.async.wait_group 0;" ::: "memory")

// block-wide exclusive prefix scan over 256 values (one per thread)
__device__ __forceinline__ float blk_exscan256(float v, int tid, float* ws) {
    float x = v;
#pragma unroll
    for (int o = 1; o < 32; o <<= 1) {
        float y = __shfl_up_sync(0xffffffffu, x, o);
        if ((tid & 31) >= o) x += y;
    }
    if ((tid & 31) == 31) ws[tid >> 5] = x;
    __syncthreads();
    float add = 0.f;
#pragma unroll
    for (int w = 0; w < 8; w++) add += (w < (tid >> 5)) ? ws[w] : 0.f;
    __syncthreads();
    return (x - v) + add;
}

// ---------------------------------------------------------------------------
// K1: batch-0 ONLY. 32 blocks. emb/u via direct warp-k-split LDG; the layer-1
// prefix c[base] computed in CLOSED FORM (monotone sc[j] => relu active on an
// interval; c = u*dP1 + bg0*dP2 via block-scanned tables + binary search),
// so NO O(N) serial scan. Layer-2 GEMM from 64KB staged smem. Emits g_h, g_P.
// grid 32 x 256, dynamic smem 64KB
// ---------------------------------------------------------------------------
__global__ void __launch_bounds__(256, 1)
k1(const float* __restrict__ z, const float* __restrict__ We,
   const float* __restrict__ be, const float* __restrict__ Wg,
   const float* __restrict__ bg) {
    extern __shared__ __align__(16) float buf[];   // 2 x 8192 floats
    __shared__ __align__(16) float gs[8][HD];
    __shared__ __align__(16) float hs[8][HD];
    __shared__ __align__(16) float4 pred[8][32];
    __shared__ float zs[64];
    __shared__ float vv[HD];
    __shared__ float uu[HD];
    __shared__ float ds[NN];     // dinv[j]
    __shared__ float scT[NN];    // sc[j] (monotone increasing)
    __shared__ float P1[NN];     // exclusive prefix of dinv[j]*sc[j]
    __shared__ float P2[NN];     // exclusive prefix of dinv[j]  (= Dex)
    __shared__ float ws[8];
    int tid = threadIdx.x, bk = blockIdx.x;
    int warp = tid >> 5, lane = tid & 31;
    uint32_t sb = (uint32_t)__cvta_generic_to_shared(buf);

    // let k2 launch + run its independent work while we execute (PDL)
    cudaTriggerProgrammaticLaunchCompletion();

    // stage layer-2 weight halves (async)
    cp_stage(sb,          Wg + HD * HD,           tid);
    cp_stage(sb + 32768u, Wg + HD * HD + 64 * HD, tid);

    // front-load emb weight LDGs (latency hidden by table build below)
    const float4* We4  = (const float4*)We;
    float4 wreg[8];
#pragma unroll
    for (int i = 0; i < 8; i++) wreg[i] = We4[(warp * 8 + i) * 32 + lane];
    if (tid < 64) zs[tid] = z[tid];

    // ---- build d-independent tables: ds, Dex->P2, sc, P1 (O(log) scans) ----
    float dv = rsqrtf((float)(tid + 1));
    ds[tid] = dv;
    float dex = blk_exscan256(dv, tid, ws);          // includes 2 syncs
    P2[tid] = dex;
    float sc = fmaf(dv, dex, dv * dv);
    scT[tid] = sc;
    float p1 = blk_exscan256(dv * sc, tid, ws);
    P1[tid] = p1;
    __syncthreads();                                  // tables + zs visible

    // emb FMAs (weights already in regs)
    {
        float4 pe = make_float4(0.f, 0.f, 0.f, 0.f);
#pragma unroll
        for (int i = 0; i < 8; i++) {
            float zk = zs[warp * 8 + i];
            pe.x = fmaf(zk, wreg[i].x, pe.x); pe.y = fmaf(zk, wreg[i].y, pe.y);
            pe.z = fmaf(zk, wreg[i].z, pe.z); pe.w = fmaf(zk, wreg[i].w, pe.w);
        }
        pred[warp][lane] = pe;
    }
    __syncthreads();
    if (tid < 32) {
        float4 s = pred[0][tid];
#pragma unroll
        for (int w = 1; w < 8; w++) {
            float4 p = pred[w][tid];
            s.x += p.x; s.y += p.y; s.z += p.z; s.w += p.w;
        }
        float4 b4 = ((const float4*)be)[tid];
        s.x += b4.x; s.y += b4.y; s.z += b4.z; s.w += b4.w;
        ((float4*)vv)[tid] = s;
    }
    __syncthreads();

    // u = vv @ Wg0: warp k-split (16 k per warp)
    {
        const float4* Wg04 = (const float4*)Wg;
        float4 pu = make_float4(0.f, 0.f, 0.f, 0.f);
#pragma unroll
        for (int i = 0; i < 16; i++) {
            int k = warp * 16 + i;
            float vk = vv[k];
            float4 w4 = Wg04[k * 32 + lane];
            pu.x = fmaf(vk, w4.x, pu.x); pu.y = fmaf(vk, w4.y, pu.y);
            pu.z = fmaf(vk, w4.z, pu.z); pu.w = fmaf(vk, w4.w, pu.w);
        }
        pred[warp][lane] = pu;
    }
    __syncthreads();
    if (tid < 32) {
        float4 s = pred[0][tid];
#pragma unroll
        for (int w = 1; w < 8; w++) {
            float4 p = pred[w][tid];
            s.x += p.x; s.y += p.y; s.z += p.z; s.w += p.w;
        }
        ((float4*)uu)[tid] = s;
    }
    __syncthreads();

    // ---- closed-form prefix + 8 local rows ----
    if (tid < 128) {
        int d = tid;
        float uf = uu[d];
        float bg0 = bg[d];
        int base = bk * 8;
        float c;
        if (base == 0) {
            c = 0.f;
        } else if (uf > 0.f) {
            // active j: sc[j]*uf + bg0 > 0, increasing -> suffix [lo, base)
            int lo = 0, hi = base;
            while (lo < hi) {
                int mid = (lo + hi) >> 1;
                if (fmaf(scT[mid], uf, bg0) > 0.f) hi = mid; else lo = mid + 1;
            }
            c = uf * (P1[base] - P1[lo]) + bg0 * (P2[base] - P2[lo]);
        } else if (uf < 0.f) {
            // expression decreasing -> active prefix [0, lo)
            int lo = 0, hi = base;
            while (lo < hi) {
                int mid = (lo + hi) >> 1;
                if (fmaf(scT[mid], uf, bg0) > 0.f) lo = mid + 1; else hi = mid;
            }
            c = uf * P1[lo] + bg0 * P2[lo];
        } else {
            c = (bg0 > 0.f) ? bg0 * P2[base] : 0.f;
        }
        // local 8 rows (same recurrence as reference)
#pragma unroll
        for (int j = 0; j < 8; j++) {
            int n = base + j;
            float dvj = ds[n];
            float h1 = fmaxf(fmaf(scT[n], uf, bg0), 0.f);
            gs[j][d] = fmaf(dvj, c, dvj * dvj * h1);
            c = fmaf(dvj, h1, c);
        }
    }
    __syncthreads();

    // layer-2 GEMM: warp-per-row, 2 staged halves
    float4 acc = ((const float4*)(bg + HD))[lane];
    CPWG1(); __syncthreads();
    {
        const float4* Ws4 = (const float4*)buf;
#pragma unroll 8
        for (int k = 0; k < 64; k++) {
            float g = gs[warp][k];
            float4 w = Ws4[k * 32 + lane];
            acc.x = fmaf(g, w.x, acc.x); acc.y = fmaf(g, w.y, acc.y);
            acc.z = fmaf(g, w.z, acc.z); acc.w = fmaf(g, w.w, acc.w);
        }
    }
    CPWG0(); __syncthreads();
    {
        const float4* Ws4 = (const float4*)(buf + 8192);
#pragma unroll 8
        for (int k = 0; k < 64; k++) {
            float g = gs[warp][64 + k];
            float4 w = Ws4[k * 32 + lane];
            acc.x = fmaf(g, w.x, acc.x); acc.y = fmaf(g, w.y, acc.y);
            acc.z = fmaf(g, w.z, acc.z); acc.w = fmaf(g, w.w, acc.w);
        }
    }
    acc.x = fmaxf(acc.x, 0.f); acc.y = fmaxf(acc.y, 0.f);
    acc.z = fmaxf(acc.z, 0.f); acc.w = fmaxf(acc.w, 0.f);
    int base = bk * 8;
    ((float4*)&g_h[base + warp][0])[lane] = acc;
    float dj = ds[base + warp];
    ((float4*)&hs[warp][0])[lane] = make_float4(acc.x * dj, acc.y * dj, acc.z * dj, acc.w * dj);
    __syncthreads();
    if (tid < HD) {
        float sum = 0.f;
#pragma unroll
        for (int w = 0; w < 8; w++) sum += hs[w][tid];
        g_P[bk][tid] = sum;
    }
}

// ---------------------------------------------------------------------------
// K2: blocks 0..63 : scan -> layer-3 GEMM+relu -> W1a|W1b GEMM (4 stages);
//                    waits on k1 only AFTER issuing its weight prefetch.
//     blocks 64..78: FULL chain for b = blk-63 (independent of k1, no
//                    gridDependencySynchronize). grid 79 x 256, smem 128KB
// ---------------------------------------------------------------------------
__global__ void __launch_bounds__(256, 1)
k2(const float* __restrict__ z, const float* __restrict__ We,
   const float* __restrict__ be, const float* __restrict__ Wg,
   const float* __restrict__ bg, const float* __restrict__ W1a,
   const float* __restrict__ W1b, const float* __restrict__ b1,
   const float* __restrict__ W2, const float* __restrict__ b2) {
    extern __shared__ __align__(16) float buf[];   // 4 x 8192 floats
    __shared__ __align__(16) float gs[8][HD];
    __shared__ __align__(16) float hs[8][HD];
    __shared__ float zs[64];
    __shared__ float vv[HD];
    __shared__ float red[2][HD];
    __shared__ float wsum[8];
    int tid = threadIdx.x, blk = blockIdx.x;
    int d = tid & 127, hf = tid >> 7;
    int warp = tid >> 5, lane = tid & 31;
    uint32_t sb = (uint32_t)__cvta_generic_to_shared(buf);
    const float* Wg2 = Wg + 2 * HD * HD;

    cudaTriggerProgrammaticLaunchCompletion();

    if (blk < 64) {
        int bk2 = blk >> 1, sel = blk & 1;
        int base = bk2 * 8;
        const float* WX = sel ? W1b : W1a;
        const float* srcs[4] = { Wg2, Wg2 + 64 * HD, WX, WX + 64 * HD };
#pragma unroll
        for (int i = 0; i < 4; i++) cp_stage(sb + i * 32768u, srcs[i], tid);

        cudaGridDependencySynchronize();

        if (tid < 128) {
            float hr[8];
#pragma unroll
            for (int j = 0; j < 8; j++) hr[j] = g_h[base + j][tid];
            float ca[4] = {0.f, 0.f, 0.f, 0.f};
#pragma unroll
            for (int p = 0; p < 32; p++) {
                float v = g_P[p][tid];
                ca[p & 3] += (p < bk2) ? v : 0.f;
            }
            float c = (ca[0] + ca[1]) + (ca[2] + ca[3]);
#pragma unroll
            for (int j = 0; j < 8; j++) {
                float dv = rsqrtf((float)(base + j + 1));
                gs[j][tid] = fmaf(dv, c, dv * dv * hr[j]);
                c = fmaf(dv, hr[j], c);
            }
        }
        float4 acc = ((const float4*)(bg + 2 * HD))[lane];
        float4 aX = sel ? make_float4(0.f, 0.f, 0.f, 0.f)
                        : ((const float4*)b1)[lane];
#pragma unroll
        for (int s = 0; s < 4; s++) {
            if (s == 0) { CPWG3(); } else if (s == 1) { CPWG2(); }
            else if (s == 2) { CPWG1(); } else { CPWG0(); }
            __syncthreads();
            const float4* Ws4 = (const float4*)(buf + s * 8192);
            const float* in = (s < 2) ? &gs[warp][0] : &hs[warp][0];
            int ko = (s & 1) * 64;
            float4 a = (s < 2) ? acc : aX;
#pragma unroll 8
            for (int k = 0; k < 64; k++) {
                float g = in[ko + k];
                float4 w = Ws4[k * 32 + lane];
                a.x = fmaf(g, w.x, a.x); a.y = fmaf(g, w.y, a.y);
                a.z = fmaf(g, w.z, a.z); a.w = fmaf(g, w.w, a.w);
            }
            if (s < 2) acc = a; else aX = a;
            if (s == 1) {
                acc.x = fmaxf(acc.x, 0.f); acc.y = fmaxf(acc.y, 0.f);
                acc.z = fmaxf(acc.z, 0.f); acc.w = fmaxf(acc.w, 0.f);
                ((float4*)&hs[warp][0])[lane] = acc;
            }
            __syncthreads();
        }
        if (sel) ((float4*)&g_B0[base + warp][0])[lane] = aX;
        else     ((float4*)&g_A0[base + warp][0])[lane] = aX;
    } else {
        int b = blk - 63;
        const float* srcs[11] = { We,
            Wg,               Wg + 64 * HD,
            Wg + HD * HD,     Wg + HD * HD + 64 * HD,
            Wg2,              Wg2 + 64 * HD,
            W1a,              W1a + 64 * HD,
            W1b,              W1b + 64 * HD };
#pragma unroll
        for (int i = 0; i < 4; i++) cp_stage(sb + i * 32768u, srcs[i], tid);
        if (tid < 64) zs[tid] = z[b * 64 + tid];
        float accL = 0.f, aA = 0.f, aB = 0.f, aAf = 0.f;
#pragma unroll
        for (int s = 0; s < 11; s++) {
            if (s <= 7) { CPWG3(); } else if (s == 8) { CPWG2(); }
            else if (s == 9) { CPWG1(); } else { CPWG0(); }
            __syncthreads();
            const float* B = buf + (s & 3) * 8192;
            if (s == 0) {
                float p0 = 0.f, p1 = 0.f; int kb = hf * 32;
#pragma unroll 8
                for (int kk = 0; kk < 32; kk += 2) {
                    p0 = fmaf(zs[kb + kk],     B[(kb + kk) * HD + d],     p0);
                    p1 = fmaf(zs[kb + kk + 1], B[(kb + kk + 1) * HD + d], p1);
                }
                red[hf][d] = p0 + p1;
                __syncthreads();
                if (tid < 128) vv[d] = red[0][d] + red[1][d] + be[d];
            } else {
                int g = (s - 1) >> 1, hh = (s - 1) & 1;
                float p0 = 0.f, p1 = 0.f; int kb = hf * 32;
#pragma unroll 8
                for (int kk = 0; kk < 32; kk += 2) {
                    p0 = fmaf(vv[hh * 64 + kb + kk],     B[(kb + kk) * HD + d],     p0);
                    p1 = fmaf(vv[hh * 64 + kb + kk + 1], B[(kb + kk + 1) * HD + d], p1);
                }
                float pt = p0 + p1;
                if (s <= 6) accL += pt;
                else if (s <= 8) aA += pt;
                else aB += pt;
                if (hh == 1 && g < 3) {
                    red[hf][d] = accL;
                    __syncthreads();
                    if (tid < 128) vv[d] = fmaxf(red[0][d] + red[1][d] + bg[g * HD + d], 0.f);
                    accL = 0.f;
                }
                if (s == 8) {
                    red[hf][d] = aA;
                    __syncthreads();
                    if (tid < 128) aAf = red[0][d] + red[1][d] + b1[d];
                }
            }
            __syncthreads();
            if (s + 4 < 11) cp_stage(sb + ((s + 4) & 3) * 32768u, srcs[s + 4], tid);
        }
        red[hf][d] = aB;
        __syncthreads();
        float t = 0.f;
        if (tid < 128) t = fmaxf(aAf + red[0][d] + red[1][d], 0.f) * W2[d];
        for (int off = 16; off > 0; off >>= 1)
            t += __shfl_down_sync(0xffffffffu, t, off);
        if ((tid & 31) == 0) wsum[tid >> 5] = t;
        __syncthreads();
        if (tid == 0) {
            float ssum = wsum[0] + wsum[1] + wsum[2] + wsum[3]
                       + wsum[4] + wsum[5] + wsum[6] + wsum[7] + b2[0];
            g_pb[b] = 1.f / (1.f + __expf(-ssum));
        }
    }
}

// ---------------------------------------------------------------------------
// K3: blocks 0..135 : batch-0 pairwise tiles (16x16, upper triangle, mirrored)
//     blocks 136..147: constant fill for b>=1 (320 rows each, diag 0)
// PDL: W2/b2 staged before the grid-dependency sync. grid 148 x 256
// ---------------------------------------------------------------------------
__global__ void k3(const float* __restrict__ W2, const float* __restrict__ b2,
                   float* __restrict__ out) {
    int tid = threadIdx.x;
    int blk = blockIdx.x;
    if (blk < 136) {
        int ti = 0, rem = blk;
        while (rem >= 16 - ti) { rem -= 16 - ti; ti++; }
        int tj = ti + rem;

        __shared__ __align__(16) float a_sh[16][132];
        __shared__ __align__(16) float b_sh[16][132];
        __shared__ __align__(16) float w2s[HD];
        __shared__ float b2s;
        __shared__ float tile[16][17];
        if (tid < HD) w2s[tid] = W2[tid];
        if (tid == 0) b2s = b2[0];

        cudaGridDependencySynchronize();

        for (int i = tid; i < 512; i += 256) {
            int r = i >> 5, d4 = i & 31;
            ((float4*)&a_sh[r][0])[d4] = ((const float4*)&g_A0[ti * 16 + r][0])[d4];
            ((float4*)&b_sh[r][0])[d4] = ((const float4*)&g_B0[tj * 16 + r][0])[d4];
        }
        __syncthreads();

        int il = tid >> 4, jl = tid & 15;
        const float4* a4 = (const float4*)&a_sh[il][0];
        const float4* b4 = (const float4*)&b_sh[jl][0];
        const float4* w4 = (const float4*)w2s;
        float ac0 = 0.f, ac1 = 0.f, ac2 = 0.f, ac3 = 0.f;
#pragma unroll
        for (int qd = 0; qd < 8; qd++) {
            { float4 a=a4[qd],    b=b4[qd],    w=w4[qd];
              ac0 = fmaf(fmaxf(a.x+b.x,0.f),w.x,ac0); ac0 = fmaf(fmaxf(a.y+b.y,0.f),w.y,ac0);
              ac0 = fmaf(fmaxf(a.z+b.z,0.f),w.z,ac0); ac0 = fmaf(fmaxf(a.w+b.w,0.f),w.w,ac0); }
            { float4 a=a4[qd+8],  b=b4[qd+8],  w=w4[qd+8];
              ac1 = fmaf(fmaxf(a.x+b.x,0.f),w.x,ac1); ac1 = fmaf(fmaxf(a.y+b.y,0.f),w.y,ac1);
              ac1 = fmaf(fmaxf(a.z+b.z,0.f),w.z,ac1); ac1 = fmaf(fmaxf(a.w+b.w,0.f),w.w,ac1); }
            { float4 a=a4[qd+16], b=b4[qd+16], w=w4[qd+16];
              ac2 = fmaf(fmaxf(a.x+b.x,0.f),w.x,ac2); ac2 = fmaf(fmaxf(a.y+b.y,0.f),w.y,ac2);
              ac2 = fmaf(fmaxf(a.z+b.z,0.f),w.z,ac2); ac2 = fmaf(fmaxf(a.w+b.w,0.f),w.w,ac2); }
            { float4 a=a4[qd+24], b=b4[qd+24], w=w4[qd+24];
              ac3 = fmaf(fmaxf(a.x+b.x,0.f),w.x,ac3); ac3 = fmaf(fmaxf(a.y+b.y,0.f),w.y,ac3);
              ac3 = fmaf(fmaxf(a.z+b.z,0.f),w.z,ac3); ac3 = fmaf(fmaxf(a.w+b.w,0.f),w.w,ac3); }
        }
        float accv = (ac0 + ac1) + (ac2 + ac3);
        tile[il][jl] = 1.f / (1.f + __expf(-(accv + b2s)));
        __syncthreads();

        int r = tid >> 4, c = tid & 15;
        if (ti == tj) {
            float vo = (r < c) ? tile[r][c] : ((r > c) ? tile[c][r] : 0.f);
            out[((size_t)(ti * 16 + r)) * NN + ti * 16 + c] = vo;
        } else {
            out[((size_t)(ti * 16 + r)) * NN + tj * 16 + c] = tile[r][c];
            out[((size_t)(tj * 16 + r)) * NN + ti * 16 + c] = tile[c][r];
        }
    } else {
        __shared__ float pbs[NB];
        cudaGridDependencySynchronize();
        if (tid < NB) pbs[tid] = g_pb[tid];
        __syncthreads();
        int fid = blk - 136;
        int f4base = fid * 20480;
#pragma unroll 4
        for (int t = 0; t < 80; t++) {
            int idx = f4base + t * 256 + tid;
            int gr = idx >> 6;
            int c4 = idx & 63;
            int b = (gr >> 8) + 1;
            int i = gr & 255;
            float p = pbs[b];
            int j0 = c4 * 4;
            float4 vo;
            vo.x = (i == j0 + 0) ? 0.f : p;
            vo.y = (i == j0 + 1) ? 0.f : p;
            vo.z = (i == j0 + 2) ? 0.f : p;
            vo.w = (i == j0 + 3) ? 0.f : p;
            ((float4*)out)[((size_t)b * NN * NN + (size_t)i * NN) / 4 + c4] = vo;
        }
    }
}

// ---------------------------------------------------------------------------
extern "C" void kernel_launch(void* const* d_in, const int* in_sizes, int n_in,
                              void* d_out, int out_size) {
    const float* z   = (const float*)d_in[0];
    const float* We  = (const float*)d_in[1];
    const float* be  = (const float*)d_in[2];
    const float* Wg  = (const float*)d_in[3];
    const float* bg  = (const float*)d_in[4];
    const float* W1a = (const float*)d_in[5];
    const float* W1b = (const float*)d_in[6];
    const float* b1  = (const float*)d_in[7];
    const float* W2  = (const float*)d_in[8];
    const float* b2  = (const float*)d_in[9];
    float* out = (float*)d_out;

    cudaFuncSetAttribute(k1, cudaFuncAttributeMaxDynamicSharedMemorySize, 65536);
    cudaFuncSetAttribute(k2, cudaFuncAttributeMaxDynamicSharedMemorySize, 131072);

    k1<<<32, 256, 65536>>>(z, We, be, Wg, bg);

    cudaLaunchAttribute attrs[1];
    attrs[0].id = cudaLaunchAttributeProgrammaticStreamSerialization;
    attrs[0].val.programmaticStreamSerializationAllowed = 1;

    {
        cudaLaunchConfig_t cfg = {};
        cfg.gridDim = dim3(79);
        cfg.blockDim = dim3(256);
        cfg.dynamicSmemBytes = 131072;
        cfg.stream = 0;
        cfg.attrs = attrs;
        cfg.numAttrs = 1;
        cudaLaunchKernelEx(&cfg, k2, z, We, be, Wg, bg, W1a, W1b, b1, W2, b2);
    }
    {
        cudaLaunchConfig_t cfg = {};
        cfg.gridDim = dim3(148);
        cfg.blockDim = dim3(256);
        cfg.dynamicSmemBytes = 0;
        cfg.stream = 0;
        cfg.attrs = attrs;
        cfg.numAttrs = 1;
        cudaLaunchKernelEx(&cfg, k3, W2, b2, out);
    }
}